// round 17
// baseline (speedup 1.0000x reference)
#include <cuda_runtime.h>
#include <cuda_fp16.h>
#include <math.h>
#include <cstdint>

#define S_TOTAL 13294
#define BATCHN 2
#define MTOT (BATCHN * S_TOTAL)   // 26588
#define DM 256
#define DF 1024

// ---------------- scratch (static device globals; no runtime allocation) -------------
__device__ __half g_qh[MTOT * DM];     // (src+pos) fp16
__device__ __half g_sh[MTOT * DM];     // src fp16
__device__ float g_offb[MTOT * DM];
__device__ float g_attn[MTOT * 128];
__device__ __half g_valh[MTOT * DM];   // value fp16
__device__ __half g_aoh[MTOT * DM];    // attention output fp16
__device__ float g_src2[MTOT * DM];
__device__ float g_x[MTOT * DM];
__device__ __half g_xh[MTOT * DM];
__device__ __half g_h1h[MTOT * DF];
__device__ float g_ff[MTOT * DM];

// transposed fp16 weights: [N][K] layout
// qproj(off|attn) 384x256 @0; val @98304; out @163840; W1 @229376; W2 @491520
#define WT_TOTAL 753664
__device__ __half g_wt[WT_TOTAL];
__device__ float g_bqa[384];

// ---------------- helpers -------------------------------------------------------------
__device__ __forceinline__ uint32_t smem_u32(const void* p) {
    uint32_t a;
    asm("{ .reg .u64 t; cvta.to.shared.u64 t, %1; cvt.u32.u64 %0, t; }" : "=r"(a) : "l"(p));
    return a;
}
__device__ __forceinline__ void ldsm_x4(uint32_t (&r)[4], uint32_t addr) {
    asm volatile("ldmatrix.sync.aligned.m8n8.x4.shared.b16 {%0,%1,%2,%3}, [%4];"
                 : "=r"(r[0]), "=r"(r[1]), "=r"(r[2]), "=r"(r[3]) : "r"(addr));
}
__device__ __forceinline__ void mma_f16(float (&c)[4], const uint32_t (&a)[4],
                                        uint32_t b0, uint32_t b1) {
    asm volatile("mma.sync.aligned.m16n8k16.row.col.f32.f16.f16.f32 "
                 "{%0,%1,%2,%3}, {%4,%5,%6,%7}, {%8,%9}, {%0,%1,%2,%3};"
                 : "+f"(c[0]), "+f"(c[1]), "+f"(c[2]), "+f"(c[3])
                 : "r"(a[0]), "r"(a[1]), "r"(a[2]), "r"(a[3]), "r"(b0), "r"(b1));
}
__device__ __forceinline__ uint32_t packh(__half a, __half b) {
    return (uint32_t)__half_as_ushort(a) | ((uint32_t)__half_as_ushort(b) << 16);
}
__device__ __forceinline__ void cp16(uint32_t dst, const void* src, bool pred) {
    int sz = pred ? 16 : 0;
    asm volatile("cp.async.cg.shared.global [%0], [%1], 16, %2;"
                 :: "r"(dst), "l"(src), "r"(sz) : "memory");
}
#define CP_COMMIT() asm volatile("cp.async.commit_group;" ::: "memory")
#define CP_WAIT(n)  asm volatile("cp.async.wait_group %0;" :: "n"(n) : "memory")

// ---------------- all weights: transpose + fp16 convert + merged bias -----------------
__global__ void convw_all(const float* __restrict__ W_off, const float* __restrict__ W_attn,
                          const float* __restrict__ W_val, const float* __restrict__ W_out,
                          const float* __restrict__ W1, const float* __restrict__ W2,
                          const float* __restrict__ b_off, const float* __restrict__ b_attn,
                          __half* __restrict__ wt, float* __restrict__ bqa) {
    int i = blockIdx.x * blockDim.x + threadIdx.x;
    if (i < 384) bqa[i] = (i < 256) ? b_off[i] : b_attn[i - 256];
    if (i >= WT_TOTAL) return;
    float x;
    if (i < 98304) {               // qproj merged: N=384, K=256
        int n = i >> 8, k = i & 255;
        x = (n < 256) ? W_off[(size_t)k * 256 + n] : W_attn[(size_t)k * 128 + (n - 256)];
    } else if (i < 163840) {       // val
        int li = i - 98304; int n = li >> 8, k = li & 255;
        x = W_val[(size_t)k * 256 + n];
    } else if (i < 229376) {       // out
        int li = i - 163840; int n = li >> 8, k = li & 255;
        x = W_out[(size_t)k * 256 + n];
    } else if (i < 491520) {       // W1: N=1024, K=256
        int li = i - 229376; int n = li >> 8, k = li & 255;
        x = W1[(size_t)k * 1024 + n];
    } else {                       // W2: N=256, K=1024
        int li = i - 491520; int n = li >> 10, k = li & 1023;
        x = W2[(size_t)k * 256 + n];
    }
    wt[i] = __float2half_rn(x);
}

// ---------------- activation convert: q = src+pos -> fp16, src -> fp16 ----------------
__global__ void qsplit(const float* __restrict__ src, const float* __restrict__ pos,
                       uint2* __restrict__ qh, uint2* __restrict__ sh, int n4) {
    int i = blockIdx.x * blockDim.x + threadIdx.x;
    if (i >= n4) return;
    float4 s = ((const float4*)src)[i];
    float4 p = ((const float4*)pos)[i];
    qh[i] = make_uint2(packh(__float2half_rn(s.x + p.x), __float2half_rn(s.y + p.y)),
                       packh(__float2half_rn(s.z + p.z), __float2half_rn(s.w + p.w)));
    sh[i] = make_uint2(packh(__float2half_rn(s.x), __float2half_rn(s.y)),
                       packh(__float2half_rn(s.z), __float2half_rn(s.w)));
}

// ---------------- fp16 tensor-core GEMM (mma.sync m16n8k16, pure fp16) ----------------
// CTA 128x64, BK=32, 8 warps (2x4), warp tile 64x16. 3 CTA/SM (regs<=85).
// cp.async 4-stage pipeline. Output: SPLITOUT -> fp16 Ch; else fp32, col<N1 -> Cf else C2f.
#define SA 40
#define ABUF_B  10240           // 128 rows * SA * 2 bytes
#define BBUF_B  5120            // 64 rows * SA * 2 bytes
#define STAGE_B 15360           // A + B
#define NSTAGE 4
#define SMEM_TOT (NSTAGE * STAGE_B)   // 61440

template <int RELU, int SPLITOUT>
__global__ void __launch_bounds__(256, 3)
tgemm(const __half* __restrict__ A, const __half* __restrict__ B,
      const float* __restrict__ bias, float* __restrict__ Cf, float* __restrict__ C2f,
      __half* __restrict__ Ch, int M, int K, int N, int N1) {
    extern __shared__ char dsm[];
    const uint32_t sb = smem_u32(dsm);

    const int t = threadIdx.x;
    const int w = t >> 5;
    const int lane = t & 31;
    const int row0 = blockIdx.y * 128;
    const int col0 = blockIdx.x * 64;
    const int wr = (w >> 2) * 64;        // warp row offset
    const int wc = (w & 3) * 16;         // warp col offset
    const int N2 = N - N1;

    const uint32_t aOff = (uint32_t)(wr * (SA * 2)) + (lane & 15) * (SA * 2) + ((lane >> 4) << 4);
    const uint32_t bOff = (uint32_t)(wc * (SA * 2)) + ((lane & 7) + ((lane >> 4) << 3)) * (SA * 2)
                        + (((lane >> 3) & 1) << 4);

    float acc[4][2][4];
#pragma unroll
    for (int i = 0; i < 4; i++)
#pragma unroll
        for (int j = 0; j < 2; j++)
#pragma unroll
            for (int r = 0; r < 4; r++) acc[i][j][r] = 0.f;

    const int nk = K >> 5;

    auto load_chunk = [&](int ch) {
        const int k0 = ch << 5;
        const uint32_t st = sb + (uint32_t)(ch % NSTAGE) * STAGE_B;
        // A: 512 uint4 (128 rows x 4), B: 256 uint4 (64 rows x 4); 3 per thread
#pragma unroll
        for (int part = 0; part < 3; part++) {
            int q = t + part * 256;
            if (q < 512) {
                int r = q >> 2;
                int c8 = (q & 3) << 3;
                uint32_t doff = (uint32_t)(r * (SA * 2) + c8 * 2);
                bool okA = (row0 + r) < M;
                size_t sA = (size_t)(row0 + r) * K + k0 + c8;
                cp16(st + doff, &A[okA ? sA : 0], okA);
            } else {
                int q2 = q - 512;
                int r = q2 >> 2;
                int c8 = (q2 & 3) << 3;
                uint32_t doff = (uint32_t)(r * (SA * 2) + c8 * 2);
                size_t sB = (size_t)(col0 + r) * K + k0 + c8;
                cp16(st + ABUF_B + doff, &B[sB], true);
            }
        }
        CP_COMMIT();
    };

    load_chunk(0);
    if (nk > 1) load_chunk(1);
    if (nk > 2) load_chunk(2);
    for (int ch = 0; ch < nk; ++ch) {
        if (ch + 3 < nk) {
            load_chunk(ch + 3);
            CP_WAIT(3);
        } else if (ch + 2 < nk) {
            CP_WAIT(2);
        } else if (ch + 1 < nk) {
            CP_WAIT(1);
        } else {
            CP_WAIT(0);
        }
        __syncthreads();

        const uint32_t st = sb + (uint32_t)(ch % NSTAGE) * STAGE_B;
        const uint32_t uA = st, uB = st + ABUF_B;
#pragma unroll
        for (int k16 = 0; k16 < 2; k16++) {
            const uint32_t kb = (uint32_t)(k16 << 5);
            uint32_t bH[4];
            ldsm_x4(bH, uB + bOff + kb);
#pragma unroll
            for (int i = 0; i < 4; i++) {
                uint32_t aF[4];
                ldsm_x4(aF, uA + aOff + i * (16 * SA * 2) + kb);
                mma_f16(acc[i][0], aF, bH[0], bH[1]);
                mma_f16(acc[i][1], aF, bH[2], bH[3]);
            }
        }
        __syncthreads();
    }

    // ---- epilogue
#pragma unroll
    for (int i = 0; i < 4; i++) {
#pragma unroll
        for (int j = 0; j < 2; j++) {
            int col = col0 + wc + j * 8 + (lane & 3) * 2;
            float bx = bias[col], by = bias[col + 1];
            int rowA = row0 + wr + i * 16 + (lane >> 2);
            int rowB = rowA + 8;
            float v0 = acc[i][j][0] + bx, v1 = acc[i][j][1] + by;
            float v2 = acc[i][j][2] + bx, v3 = acc[i][j][3] + by;
            if (RELU) {
                v0 = fmaxf(v0, 0.f); v1 = fmaxf(v1, 0.f);
                v2 = fmaxf(v2, 0.f); v3 = fmaxf(v3, 0.f);
            }
            if (SPLITOUT) {
                if (rowA < M)
                    *(uint32_t*)&Ch[(size_t)rowA * N + col] = packh(__float2half_rn(v0), __float2half_rn(v1));
                if (rowB < M)
                    *(uint32_t*)&Ch[(size_t)rowB * N + col] = packh(__float2half_rn(v2), __float2half_rn(v3));
            } else if (col < N1) {
                if (rowA < M) *(float2*)&Cf[(size_t)rowA * N1 + col] = make_float2(v0, v1);
                if (rowB < M) *(float2*)&Cf[(size_t)rowB * N1 + col] = make_float2(v2, v3);
            } else {
                int c2 = col - N1;
                if (rowA < M) *(float2*)&C2f[(size_t)rowA * N2 + c2] = make_float2(v0, v1);
                if (rowB < M) *(float2*)&C2f[(size_t)rowB * N2 + c2] = make_float2(v2, v3);
            }
        }
    }
}

// ---------------- fused msda: prep in smem + gather -----------------------------------
__global__ void __launch_bounds__(256) msda_fused(
    const float* __restrict__ refp, const float* __restrict__ off,
    const float* __restrict__ attnlog, const __half* __restrict__ valh,
    __half* __restrict__ outh) {
    __shared__ int4   sidx[128];
    __shared__ float4 sw[128];

    const int row = blockIdx.x;
    const int t = threadIdx.x;
    const int n = (row >= S_TOTAL) ? 1 : 0;

    if (t < 128) {
        const int h = t >> 4;       // head
        const int p = t & 15;       // point (lv*4 + pp)
        const int lv = p >> 2;

        float lg = attnlog[(size_t)row * 128 + h * 16 + p];
        float m = lg;
#pragma unroll
        for (int msk = 8; msk; msk >>= 1)
            m = fmaxf(m, __shfl_xor_sync(0xffffffffu, m, msk, 16));
        float e = __expf(lg - m);
        float den = e;
#pragma unroll
        for (int msk = 8; msk; msk >>= 1)
            den += __shfl_xor_sync(0xffffffffu, den, msk, 16);
        float aw = e / den;

        const int H = (lv == 0) ? 100 : (lv == 1) ? 50 : (lv == 2) ? 25 : 13;
        const int W = H;
        const int start = (lv == 0) ? 0 : (lv == 1) ? 10000 : (lv == 2) ? 12500 : 13125;
        const int base = n * S_TOTAL + start;

        float2 o = ((const float2*)(off + (size_t)row * 256 + h * 32))[p];
        float rx = refp[(size_t)row * 8 + lv * 2 + 0];
        float ry = refp[(size_t)row * 8 + lv * 2 + 1];

        float x = (rx + o.x / (float)W) * (float)W - 0.5f;
        float y = (ry + o.y / (float)H) * (float)H - 0.5f;
        float x0f = floorf(x), y0f = floorf(y);
        int x0 = (int)x0f, y0 = (int)y0f;
        int x1 = x0 + 1, y1 = y0 + 1;
        float wx1 = x - x0f, wx0 = 1.f - wx1;
        float wy1 = y - y0f, wy0 = 1.f - wy1;

        float fx0 = ((unsigned)x0 < (unsigned)W) ? 1.f : 0.f;
        float fx1 = ((unsigned)x1 < (unsigned)W) ? 1.f : 0.f;
        float fy0 = ((unsigned)y0 < (unsigned)H) ? 1.f : 0.f;
        float fy1 = ((unsigned)y1 < (unsigned)H) ? 1.f : 0.f;
        int xc0 = min(max(x0, 0), W - 1);
        int xc1 = min(max(x1, 0), W - 1);
        int yc0 = min(max(y0, 0), H - 1);
        int yc1 = min(max(y1, 0), H - 1);

        int4 idx;
        idx.x = base + yc0 * W + xc0;
        idx.y = base + yc0 * W + xc1;
        idx.z = base + yc1 * W + xc0;
        idx.w = base + yc1 * W + xc1;
        float4 wv;
        wv.x = aw * wy0 * wx0 * fy0 * fx0;
        wv.y = aw * wy0 * wx1 * fy0 * fx1;
        wv.z = aw * wy1 * wx0 * fy1 * fx0;
        wv.w = aw * wy1 * wx1 * fy1 * fx1;
        sidx[t] = idx;
        sw[t] = wv;
    }
    __syncthreads();

    const int h = t >> 5;
    const int lane = t & 31;
    const __half* vp = valh + h * 32 + lane;

    float acc = 0.f;
#pragma unroll
    for (int p = 0; p < 16; p++) {
        int4 id = sidx[h * 16 + p];
        float4 wv = sw[h * 16 + p];
        acc = fmaf(wv.x, __half2float(vp[(size_t)id.x << 8]), acc);
        acc = fmaf(wv.y, __half2float(vp[(size_t)id.y << 8]), acc);
        acc = fmaf(wv.z, __half2float(vp[(size_t)id.z << 8]), acc);
        acc = fmaf(wv.w, __half2float(vp[(size_t)id.w << 8]), acc);
    }
    outh[(size_t)row * 256 + h * 32 + lane] = __float2half_rn(acc);
}

// ---------------- fused residual add + LayerNorm (C=256), optional fp16 out -----------
template <int SPLIT>
__global__ void __launch_bounds__(256) add_ln(const float* __restrict__ a,
                                              const float* __restrict__ b,
                                              const float* __restrict__ g,
                                              const float* __restrict__ be,
                                              float* __restrict__ out,
                                              __half* __restrict__ oh) {
    int row = blockIdx.x;
    int t = threadIdx.x;
    float v = a[(size_t)row * 256 + t] + b[(size_t)row * 256 + t];

    __shared__ float red[8];
    __shared__ float stat[2];

    float s = v;
#pragma unroll
    for (int o = 16; o; o >>= 1) s += __shfl_xor_sync(0xffffffffu, s, o);
    if ((t & 31) == 0) red[t >> 5] = s;
    __syncthreads();
    if (t == 0) {
        float tot = 0.f;
        for (int i = 0; i < 8; i++) tot += red[i];
        stat[0] = tot * (1.f / 256.f);
    }
    __syncthreads();
    float mean = stat[0];
    float d = v - mean;

    s = d * d;
#pragma unroll
    for (int o = 16; o; o >>= 1) s += __shfl_xor_sync(0xffffffffu, s, o);
    __syncthreads();
    if ((t & 31) == 0) red[t >> 5] = s;
    __syncthreads();
    if (t == 0) {
        float tot = 0.f;
        for (int i = 0; i < 8; i++) tot += red[i];
        stat[1] = tot * (1.f / 256.f);
    }
    __syncthreads();
    float var = stat[1];

    float y = d * rsqrtf(var + 1e-5f) * g[t] + be[t];
    out[(size_t)row * 256 + t] = y;
    if (SPLIT) oh[(size_t)row * 256 + t] = __float2half_rn(y);
}

// ---------------- launch -------------------------------------------------------------
extern "C" void kernel_launch(void* const* d_in, const int* in_sizes, int n_in,
                              void* d_out, int out_size) {
    const float* src   = (const float*)d_in[0];
    const float* pos   = (const float*)d_in[1];
    const float* refp  = (const float*)d_in[2];
    const float* W_off  = (const float*)d_in[5];
    const float* b_off  = (const float*)d_in[6];
    const float* W_attn = (const float*)d_in[7];
    const float* b_attn = (const float*)d_in[8];
    const float* W_val  = (const float*)d_in[9];
    const float* b_val  = (const float*)d_in[10];
    const float* W_out  = (const float*)d_in[11];
    const float* b_out  = (const float*)d_in[12];
    const float* W1     = (const float*)d_in[13];
    const float* b1     = (const float*)d_in[14];
    const float* W2     = (const float*)d_in[15];
    const float* b2     = (const float*)d_in[16];
    const float* g1p    = (const float*)d_in[17];
    const float* be1p   = (const float*)d_in[18];
    const float* g2p    = (const float*)d_in[19];
    const float* be2p   = (const float*)d_in[20];
    float* out = (float*)d_out;

    __half *qh, *sh, *valh, *aoh, *xh, *h1h;
    float *offb, *attn, *src2, *x, *ff, *bqa;
    cudaGetSymbolAddress((void**)&qh, g_qh);     cudaGetSymbolAddress((void**)&sh, g_sh);
    cudaGetSymbolAddress((void**)&offb, g_offb); cudaGetSymbolAddress((void**)&attn, g_attn);
    cudaGetSymbolAddress((void**)&valh, g_valh); cudaGetSymbolAddress((void**)&aoh, g_aoh);
    cudaGetSymbolAddress((void**)&src2, g_src2); cudaGetSymbolAddress((void**)&x, g_x);
    cudaGetSymbolAddress((void**)&xh, g_xh);     cudaGetSymbolAddress((void**)&h1h, g_h1h);
    cudaGetSymbolAddress((void**)&ff, g_ff);     cudaGetSymbolAddress((void**)&bqa, g_bqa);

    __half *wt;
    cudaGetSymbolAddress((void**)&wt, g_wt);
    __half *qpw = wt + 0;            // merged off|attn, N=384
    __half *valw = wt + 98304;
    __half *outw = wt + 163840;
    __half *w1w  = wt + 229376;
    __half *w2w  = wt + 491520;

    cudaFuncSetAttribute(tgemm<0, 0>, cudaFuncAttributeMaxDynamicSharedMemorySize, SMEM_TOT);
    cudaFuncSetAttribute(tgemm<0, 1>, cudaFuncAttributeMaxDynamicSharedMemorySize, SMEM_TOT);
    cudaFuncSetAttribute(tgemm<1, 1>, cudaFuncAttributeMaxDynamicSharedMemorySize, SMEM_TOT);

    const int M = MTOT;
    const int mby = (M + 127) / 128;   // 208
    const int n4 = M * DM / 4;

    convw_all<<<(WT_TOTAL + 255) / 256, 256>>>(W_off, W_attn, W_val, W_out, W1, W2,
                                               b_off, b_attn, wt, bqa);
    qsplit<<<(n4 + 255) / 256, 256>>>(src, pos, (uint2*)qh, (uint2*)sh, n4);

    // merged qproj: cols 0..255 -> offb, 256..383 -> attn
    tgemm<0, 0><<<dim3(6, mby), 256, SMEM_TOT>>>(qh, qpw, bqa, offb, attn, nullptr, M, 256, 384, 256);
    // value projection -> fp16
    tgemm<0, 1><<<dim3(4, mby), 256, SMEM_TOT>>>(sh, valw, b_val, nullptr, nullptr, valh, M, 256, 256, 256);

    msda_fused<<<M, 256>>>(refp, offb, attn, valh, aoh);

    tgemm<0, 0><<<dim3(4, mby), 256, SMEM_TOT>>>(aoh, outw, b_out, src2, nullptr, nullptr, M, 256, 256, 256);
    add_ln<1><<<M, 256>>>(src, src2, g1p, be1p, x, xh);

    tgemm<1, 1><<<dim3(16, mby), 256, SMEM_TOT>>>(xh, w1w, b1, nullptr, nullptr, h1h, M, 256, 1024, 1024);
    tgemm<0, 0><<<dim3(4, mby), 256, SMEM_TOT>>>(h1h, w2w, b2, ff, nullptr, nullptr, M, 1024, 256, 256);
    add_ln<0><<<M, 256>>>(x, ff, g2p, be2p, out, nullptr);
}